// round 9
// baseline (speedup 1.0000x reference)
#include <cuda_runtime.h>
#include <cuda_bf16.h>
#include <cstdint>
#include <math.h>

// ---------------------------------------------------------------------------
// Self-attention B=4, S=2048, D=1024 — Round 8.
// bf16x3-split GEMMs (mma.sync.m16n8k16), operands pre-split in gmem.
// GEMM: 128x128 block tile, 4 warps (2x2), warp tile 64x64 -> 96 HMMA per
// 16 ldmatrix per k16 step (ratio 6 vs 4 before). BKE=32, 2-stage cp.async,
// 80KB smem/CTA -> 2 CTAs/SM.
// ---------------------------------------------------------------------------

#define BATCH 4
#define SEQ   2048
#define DIM   1024

typedef __nv_bfloat16 bf16;

// ---------------- scratch ---------------------------------------------------
__device__ bf16  g_ah[BATCH * SEQ * DIM], g_al[BATCH * SEQ * DIM];
__device__ bf16  g_wth[3 * DIM * DIM],    g_wtl[3 * DIM * DIM];
__device__ bf16  g_qh[BATCH * SEQ * DIM], g_ql[BATCH * SEQ * DIM];
__device__ bf16  g_kh[BATCH * SEQ * DIM], g_kl[BATCH * SEQ * DIM];
__device__ bf16  g_vh[BATCH * SEQ * DIM], g_vl[BATCH * SEQ * DIM];
__device__ bf16  g_vth[BATCH * DIM * SEQ], g_vtl[BATCH * DIM * SEQ];
__device__ float g_s [BATCH * SEQ * SEQ];
__device__ bf16  g_ph[BATCH * SEQ * SEQ], g_pl[BATCH * SEQ * SEQ];

// ---------------- helpers ---------------------------------------------------
__device__ __forceinline__ uint32_t smem_u32(const void* p) {
    uint32_t a;
    asm("{ .reg .u64 t; cvta.to.shared.u64 t, %1; cvt.u32.u64 %0, t; }"
        : "=r"(a) : "l"(p));
    return a;
}
__device__ __forceinline__ void cp16(uint32_t dst, const void* src) {
    asm volatile("cp.async.cg.shared.global [%0], [%1], 16;"
                 :: "r"(dst), "l"(src));
}
#define CP_COMMIT() asm volatile("cp.async.commit_group;" ::: "memory")
#define CP_WAIT(n)  asm volatile("cp.async.wait_group %0;" :: "n"(n) : "memory")

__device__ __forceinline__ void ldm_x4(uint32_t* r, uint32_t addr) {
    asm volatile("ldmatrix.sync.aligned.m8n8.x4.shared.b16 {%0,%1,%2,%3}, [%4];"
                 : "=r"(r[0]), "=r"(r[1]), "=r"(r[2]), "=r"(r[3]) : "r"(addr));
}
__device__ __forceinline__ void mma_bf16(float* c, const uint32_t* a,
                                         const uint32_t* b) {
    asm volatile(
        "mma.sync.aligned.m16n8k16.row.col.f32.bf16.bf16.f32 "
        "{%0,%1,%2,%3}, {%4,%5,%6,%7}, {%8,%9}, {%0,%1,%2,%3};"
        : "+f"(c[0]), "+f"(c[1]), "+f"(c[2]), "+f"(c[3])
        : "r"(a[0]), "r"(a[1]), "r"(a[2]), "r"(a[3]), "r"(b[0]), "r"(b[1]));
}
__device__ __forceinline__ uint32_t bpack(bf16 a, bf16 b) {
    union { __nv_bfloat162 v; uint32_t u; } t;
    t.v = __halves2bfloat162(a, b);
    return t.u;
}
__device__ __forceinline__ void split2(float x, float y, uint32_t& hi,
                                       uint32_t& lo) {
    bf16 hx = __float2bfloat16(x), hy = __float2bfloat16(y);
    hi = bpack(hx, hy);
    lo = bpack(__float2bfloat16(x - __bfloat162float(hx)),
               __float2bfloat16(y - __bfloat162float(hy)));
}

// ---------------- GEMM config ----------------------------------------------
#define BM 128
#define BN 128
#define BKE 32                 // bf16 elems per stage (2 x k16)
#define GTHREADS 128           // 4 warps: 2(M) x 2(N), warp tile 64x64

#define ROWB   80              // 64B data + 16B pad
#define TILEB  (128 * ROWB)    // 10240
#define ST_AHI 0
#define ST_ALO (TILEB)
#define ST_BHI (2 * TILEB)
#define ST_BLO (3 * TILEB)
#define STAGEB (4 * TILEB)     // 40960
#define SMEM_SZ (2 * STAGEB)   // 81920 -> 2 CTAs/SM

// issue one tile (128 rows x 32 bf16) into a smem slot
__device__ __forceinline__ void issue_tile(const bf16* src, uint32_t dst,
                                           int K, long k0, int tid) {
#pragma unroll
    for (int it = 0; it < 4; it++) {
        int c = tid + it * GTHREADS;          // 0..511
        int row = c >> 2, col = c & 3;
        cp16(dst + row * ROWB + col * 16, src + (long)row * K + k0 + col * 8);
    }
}

// NT GEMM: C[m][n] = sum_k A[m][k]*B[n][k]; A,B as hi/lo bf16 pairs.
template<bool HAS_BIAS, bool SPLIT_OUT>
__global__ void __launch_bounds__(GTHREADS, 2)
bf16x3_gemm(const bf16* __restrict__ Ah, const bf16* __restrict__ Al,
            const bf16* __restrict__ Bh, const bf16* __restrict__ Bl,
            const float* __restrict__ bias,
            float* __restrict__ Cf, bf16* __restrict__ Ch,
            bf16* __restrict__ Cl,
            int M, int N, int K, long sA, long sB, long sC)
{
    extern __shared__ char smem[];
    const uint32_t sbase = smem_u32(smem);
    const int tid  = threadIdx.x;
    const int lane = tid & 31;
    const int wid  = tid >> 5;
    const int wm0  = (wid >> 1) * 64;     // 0 / 64
    const int wn0  = (wid & 1) * 64;      // 0 / 64
    const int m0 = blockIdx.y * BM;
    const int n0 = blockIdx.x * BN;

    const bf16* Ahb = Ah + (long)blockIdx.z * sA + (long)m0 * K;
    const bf16* Alb = Al + (long)blockIdx.z * sA + (long)m0 * K;
    const bf16* Bhb = Bh + (long)blockIdx.z * sB + (long)n0 * K;
    const bf16* Blb = Bl + (long)blockIdx.z * sB + (long)n0 * K;

    const uint32_t partA = (uint32_t)((wm0 + (lane & 15)) * ROWB
                                      + ((lane >> 4) << 4));
    const uint32_t partB = (uint32_t)((wn0 + (lane & 7) + ((lane >> 4) << 3)) * ROWB
                                      + ((lane & 8) ? 16 : 0));

    float acc[4][8][4];
#pragma unroll
    for (int i = 0; i < 4; i++)
#pragma unroll
        for (int j = 0; j < 8; j++)
#pragma unroll
            for (int r = 0; r < 4; r++) acc[i][j][r] = 0.f;

    const int NC = K / BKE;

    // prologue: stage 0
    issue_tile(Ahb, sbase + ST_AHI, K, 0, tid);
    issue_tile(Alb, sbase + ST_ALO, K, 0, tid);
    issue_tile(Bhb, sbase + ST_BHI, K, 0, tid);
    issue_tile(Blb, sbase + ST_BLO, K, 0, tid);
    CP_COMMIT();

    for (int i = 0; i < NC; i++) {
        __syncthreads();   // readers of the other slot are done
        if (i + 1 < NC) {
            uint32_t sb = sbase + (uint32_t)(((i + 1) & 1) * STAGEB);
            long k0 = (long)(i + 1) * BKE;
            issue_tile(Ahb, sb + ST_AHI, K, k0, tid);
            issue_tile(Alb, sb + ST_ALO, K, k0, tid);
            issue_tile(Bhb, sb + ST_BHI, K, k0, tid);
            issue_tile(Blb, sb + ST_BLO, K, k0, tid);
            CP_COMMIT();
            CP_WAIT(1);    // stage i resident
        } else {
            CP_WAIT(0);
        }
        __syncthreads();

        const uint32_t st = sbase + (uint32_t)((i & 1) * STAGEB);
#pragma unroll
        for (int ks = 0; ks < 2; ks++) {
            uint32_t ah[4][4], al[4][4];
#pragma unroll
            for (int mf = 0; mf < 4; mf++) {
                uint32_t off = (uint32_t)(mf * 16 * ROWB + ks * 32) + partA;
                ldm_x4(ah[mf], st + ST_AHI + off);
                ldm_x4(al[mf], st + ST_ALO + off);
            }
#pragma unroll
            for (int nf2 = 0; nf2 < 4; nf2++) {
                uint32_t off = (uint32_t)(nf2 * 16 * ROWB + ks * 32) + partB;
                uint32_t bh[2][2], bl[2][2], t[4];
                ldm_x4(t, st + ST_BHI + off);
                bh[0][0] = t[0]; bh[0][1] = t[1];
                bh[1][0] = t[2]; bh[1][1] = t[3];
                ldm_x4(t, st + ST_BLO + off);
                bl[0][0] = t[0]; bl[0][1] = t[1];
                bl[1][0] = t[2]; bl[1][1] = t[3];
#pragma unroll
                for (int nn = 0; nn < 2; nn++) {
                    const int nf = nf2 * 2 + nn;
#pragma unroll
                    for (int mf = 0; mf < 4; mf++) {
                        mma_bf16(acc[mf][nf], ah[mf], bh[nn]);
                        mma_bf16(acc[mf][nf], ah[mf], bl[nn]);
                        mma_bf16(acc[mf][nf], al[mf], bh[nn]);
                    }
                }
            }
        }
    }

    // epilogue
    const int gid = lane >> 2, tig = lane & 3;
#pragma unroll
    for (int mf = 0; mf < 4; mf++) {
        int r0 = m0 + wm0 + mf * 16 + gid;
#pragma unroll
        for (int nf = 0; nf < 8; nf++) {
            int c0 = n0 + wn0 + nf * 8 + tig * 2;
            float bx = 0.f, by = 0.f;
            if (HAS_BIAS) { bx = bias[c0]; by = bias[c0 + 1]; }
            float x0 = acc[mf][nf][0] + bx, y0 = acc[mf][nf][1] + by;
            float x1 = acc[mf][nf][2] + bx, y1 = acc[mf][nf][3] + by;
            if (SPLIT_OUT) {
                long o0 = (long)(r0) * N + c0 + (long)blockIdx.z * sC;
                long o1 = (long)(r0 + 8) * N + c0 + (long)blockIdx.z * sC;
                uint32_t h, l;
                split2(x0, y0, h, l);
                *(uint32_t*)(Ch + o0) = h; *(uint32_t*)(Cl + o0) = l;
                split2(x1, y1, h, l);
                *(uint32_t*)(Ch + o1) = h; *(uint32_t*)(Cl + o1) = l;
            } else {
                float* Cb = Cf + (long)blockIdx.z * sC;
                *(float2*)(Cb + (long)r0 * N + c0) = make_float2(x0, y0);
                *(float2*)(Cb + (long)(r0 + 8) * N + c0) = make_float2(x1, y1);
            }
        }
    }
}

// ---------------- split a ---------------------------------------------------
__global__ void __launch_bounds__(256)
split_kernel(const float* __restrict__ src, bf16* __restrict__ h,
             bf16* __restrict__ l)
{
    long idx = (long)blockIdx.x * 256 + threadIdx.x;
    float2 v = ((const float2*)src)[idx];
    uint32_t hw, lw;
    split2(v.x, v.y, hw, lw);
    ((uint32_t*)h)[idx] = hw;
    ((uint32_t*)l)[idx] = lw;
}

// ---------------- weight transpose + split ----------------------------------
__global__ void __launch_bounds__(256)
wsplit_kernel(const float* __restrict__ w, bf16* __restrict__ h,
              bf16* __restrict__ l)
{
    __shared__ float t[32][33];
    int x = blockIdx.x * 32 + threadIdx.x;
    int y = blockIdx.y * 32 + threadIdx.y;
#pragma unroll
    for (int j = 0; j < 32; j += 8)
        t[threadIdx.y + j][threadIdx.x] = w[(long)(y + j) * DIM + x];
    __syncthreads();
    x = blockIdx.y * 32 + threadIdx.x;
    y = blockIdx.x * 32 + threadIdx.y;
#pragma unroll
    for (int j = 0; j < 32; j += 8) {
        float v = t[threadIdx.x][threadIdx.y + j];
        bf16 hv = __float2bfloat16(v);
        h[(long)(y + j) * DIM + x] = hv;
        l[(long)(y + j) * DIM + x] =
            __float2bfloat16(v - __bfloat162float(hv));
    }
}

// ---------------- bf16 transpose --------------------------------------------
__global__ void __launch_bounds__(256)
transpose_bf16(const uint16_t* __restrict__ src, uint16_t* __restrict__ dst,
               int R, int C, long sS, long sD)
{
    __shared__ uint16_t t[32][33];
    src += (long)blockIdx.z * sS;
    dst += (long)blockIdx.z * sD;
    int x = blockIdx.x * 32 + threadIdx.x;
    int y = blockIdx.y * 32 + threadIdx.y;
#pragma unroll
    for (int j = 0; j < 32; j += 8)
        t[threadIdx.y + j][threadIdx.x] = src[(long)(y + j) * C + x];
    __syncthreads();
    x = blockIdx.y * 32 + threadIdx.x;
    y = blockIdx.x * 32 + threadIdx.y;
#pragma unroll
    for (int j = 0; j < 32; j += 8)
        dst[(long)(y + j) * R + x] = t[threadIdx.x][threadIdx.y + j];
}

// ---------------- softmax -> hi/lo ------------------------------------------
__global__ void __launch_bounds__(256)
softmax_split(const float* __restrict__ S, bf16* __restrict__ Ph,
              bf16* __restrict__ Pl)
{
    const float2* row = (const float2*)(S + (long)blockIdx.x * SEQ);
    uint32_t* oh = (uint32_t*)(Ph + (long)blockIdx.x * SEQ);
    uint32_t* ol = (uint32_t*)(Pl + (long)blockIdx.x * SEQ);
    __shared__ float red[256];
    const int tid = threadIdx.x;

    float2 e[4];
#pragma unroll
    for (int j = 0; j < 4; j++) e[j] = row[tid + j * 256];

    float m = -INFINITY;
#pragma unroll
    for (int j = 0; j < 4; j++) m = fmaxf(m, fmaxf(e[j].x, e[j].y));
    red[tid] = m;
    __syncthreads();
    for (int s = 128; s > 0; s >>= 1) {
        if (tid < s) red[tid] = fmaxf(red[tid], red[tid + s]);
        __syncthreads();
    }
    m = red[0];
    __syncthreads();

    float sum = 0.f;
#pragma unroll
    for (int j = 0; j < 4; j++) {
        e[j].x = __expf(e[j].x - m);
        e[j].y = __expf(e[j].y - m);
        sum += e[j].x + e[j].y;
    }
    red[tid] = sum;
    __syncthreads();
    for (int s = 128; s > 0; s >>= 1) {
        if (tid < s) red[tid] += red[tid + s];
        __syncthreads();
    }
    float inv = 1.f / red[0];

#pragma unroll
    for (int j = 0; j < 4; j++) {
        uint32_t h, l;
        split2(e[j].x * inv, e[j].y * inv, h, l);
        oh[tid + j * 256] = h;
        ol[tid + j * 256] = l;
    }
}

// ---------------------------------------------------------------------------
extern "C" void kernel_launch(void* const* d_in, const int* in_sizes, int n_in,
                              void* d_out, int out_size)
{
    const float* a   = (const float*)d_in[0];
    const float* w_q = (const float*)d_in[1];
    const float* b_q = (const float*)d_in[2];
    const float* w_k = (const float*)d_in[3];
    const float* b_k = (const float*)d_in[4];
    const float* w_v = (const float*)d_in[5];
    const float* b_v = (const float*)d_in[6];
    float* out = (float*)d_out;

    bf16 *ah, *al, *wth, *wtl, *qh, *ql, *kh, *kl, *vh, *vl, *vth, *vtl, *ph, *pl;
    float* s;
    cudaGetSymbolAddress((void**)&ah,  g_ah);  cudaGetSymbolAddress((void**)&al,  g_al);
    cudaGetSymbolAddress((void**)&wth, g_wth); cudaGetSymbolAddress((void**)&wtl, g_wtl);
    cudaGetSymbolAddress((void**)&qh,  g_qh);  cudaGetSymbolAddress((void**)&ql,  g_ql);
    cudaGetSymbolAddress((void**)&kh,  g_kh);  cudaGetSymbolAddress((void**)&kl,  g_kl);
    cudaGetSymbolAddress((void**)&vh,  g_vh);  cudaGetSymbolAddress((void**)&vl,  g_vl);
    cudaGetSymbolAddress((void**)&vth, g_vth); cudaGetSymbolAddress((void**)&vtl, g_vtl);
    cudaGetSymbolAddress((void**)&ph,  g_ph);  cudaGetSymbolAddress((void**)&pl,  g_pl);
    cudaGetSymbolAddress((void**)&s,   g_s);

    cudaFuncSetAttribute(bf16x3_gemm<true, true>,
                         cudaFuncAttributeMaxDynamicSharedMemorySize, SMEM_SZ);
    cudaFuncSetAttribute(bf16x3_gemm<false, false>,
                         cudaFuncAttributeMaxDynamicSharedMemorySize, SMEM_SZ);

    const int M1 = BATCH * SEQ;   // 8192

    // 0) operand prep
    split_kernel<<<(long)M1 * DIM / 512, 256>>>(a, ah, al);
    {
        dim3 grid(DIM / 32, DIM / 32, 1);
        dim3 blk(32, 8, 1);
        wsplit_kernel<<<grid, blk>>>(w_q, wth + 0L * DIM * DIM, wtl + 0L * DIM * DIM);
        wsplit_kernel<<<grid, blk>>>(w_k, wth + 1L * DIM * DIM, wtl + 1L * DIM * DIM);
        wsplit_kernel<<<grid, blk>>>(w_v, wth + 2L * DIM * DIM, wtl + 2L * DIM * DIM);
    }

    // 1) projections -> hi/lo outputs
    {
        dim3 grid(DIM / BN, M1 / BM, 1);
        bf16x3_gemm<true, true><<<grid, GTHREADS, SMEM_SZ>>>(
            ah, al, wth + 0L * DIM * DIM, wtl + 0L * DIM * DIM, b_q,
            nullptr, qh, ql, M1, DIM, DIM, 0, 0, 0);
        bf16x3_gemm<true, true><<<grid, GTHREADS, SMEM_SZ>>>(
            ah, al, wth + 1L * DIM * DIM, wtl + 1L * DIM * DIM, b_k,
            nullptr, kh, kl, M1, DIM, DIM, 0, 0, 0);
        bf16x3_gemm<true, true><<<grid, GTHREADS, SMEM_SZ>>>(
            ah, al, wth + 2L * DIM * DIM, wtl + 2L * DIM * DIM, b_v,
            nullptr, vh, vl, M1, DIM, DIM, 0, 0, 0);
    }

    // 2) vt h/l = transpose(v h/l)
    {
        dim3 grid(DIM / 32, SEQ / 32, BATCH);
        dim3 blk(32, 8, 1);
        transpose_bf16<<<grid, blk>>>((const uint16_t*)vh, (uint16_t*)vth,
                                      SEQ, DIM, (long)SEQ * DIM, (long)DIM * SEQ);
        transpose_bf16<<<grid, blk>>>((const uint16_t*)vl, (uint16_t*)vtl,
                                      SEQ, DIM, (long)SEQ * DIM, (long)DIM * SEQ);
    }

    // 3) scores = q @ k^T (fp32 out)
    {
        dim3 grid(SEQ / BN, SEQ / BM, BATCH);
        bf16x3_gemm<false, false><<<grid, GTHREADS, SMEM_SZ>>>(
            qh, ql, kh, kl, nullptr, s, nullptr, nullptr,
            SEQ, SEQ, DIM, (long)SEQ * DIM, (long)SEQ * DIM, (long)SEQ * SEQ);
    }

    // 4) softmax -> p hi/lo
    softmax_split<<<BATCH * SEQ, 256>>>(s, ph, pl);

    // 5) out = p @ vt^T (fp32 out)
    {
        dim3 grid(DIM / BN, SEQ / BM, BATCH);
        bf16x3_gemm<false, false><<<grid, GTHREADS, SMEM_SZ>>>(
            ph, pl, vth, vtl, nullptr, out, nullptr, nullptr,
            SEQ, DIM, SEQ, (long)SEQ * SEQ, (long)DIM * SEQ, (long)SEQ * DIM);
    }
}